// round 10
// baseline (speedup 1.0000x reference)
#include <cuda_runtime.h>
#include <cstdint>

// LengthRegulator: expand hidden_phonems [B,L,D] by durations [B,L] into
// out [B, max_T, D], zero-padded beyond totals[b].
//
// R10: TMA bulk-store replication from UNIQUE rows. SIMT formulations all
// converge to ~13.5us because the SIMT STG path drives LTS at only ~42%.
// Here each block stages its 16 phoneme rows in SMEM (each row twice ->
// 2KB contiguous), then elected lanes issue ceil(d/2) cp.async.bulk S2G
// copies per phoneme; the TMA engine does the 59MB of global writes.
// SIMT bytes: 16MB LDG + 32MB STS only. Tail zeroed via bulks of a zero row.

#define B_CONST 32
#define L_CONST 512
#define D_CONST 256
#define D4 (D_CONST / 4)
#define MAX_DUR 8
#define P_PER_BLK 16
#define BLOCKS_PER_BATCH (L_CONST / P_PER_BLK)   // 32
#define THREADS 128
#define ROW_F4 (D4)                               // 64 float4 = 1KB
#define FRAME_BYTES (D_CONST * 4)                 // 1024

__device__ __forceinline__ uint32_t smem_u32(const void* p) {
    uint32_t a;
    asm("{ .reg .u64 tmp; cvta.to.shared.u64 tmp, %1; cvt.u32.u64 %0, tmp; }"
        : "=r"(a) : "l"(p));
    return a;
}

__global__ void __launch_bounds__(THREADS) lr_fused(
    const float4* __restrict__ hidden4,
    const int*    __restrict__ durations,
    float4*       __restrict__ out4,
    int max_T)
{
    // each row staged twice -> 2KB contiguous per phoneme (for 2-frame bulks)
    __shared__ float4 rows[P_PER_BLK * 2 * ROW_F4];   // 32KB
    __shared__ float4 zrow[ROW_F4];                   // 1KB zero frame

    const int t        = threadIdx.x;             // 0..127
    const int w        = t >> 5;                  // warp [0,4)
    const int lane     = t & 31;
    const int blk      = blockIdx.x;              // 0..1023
    const int b        = blk >> 5;                // batch
    const int blkLocal = blk & (BLOCKS_PER_BATCH - 1);
    const int l0       = blkLocal * P_PER_BLK;    // multiple of 16
    const int lw       = l0 + 4 * w;              // this warp's first phoneme

    const int* __restrict__ dbat = durations + b * L_CONST;

    // ---- stage 16 rows, each replicated twice (coalesced LDG -> 2x STS)
    #pragma unroll
    for (int i = 0; i < 8; ++i) {
        const int idx = t + THREADS * i;          // 0..1023
        const int r   = idx >> 6;                 // row 0..15
        const int c   = idx & 63;
        const float4 v = hidden4[((size_t)b * L_CONST + l0 + r) * D4 + c];
        rows[r * 2 * ROW_F4 + c]          = v;
        rows[r * 2 * ROW_F4 + ROW_F4 + c] = v;
    }
    if (t < ROW_F4) zrow[t] = make_float4(0.f, 0.f, 0.f, 0.f);

    // ---- per-warp packed reduction over the 512 durations:
    //      low 16 = batch total, high 16 = exclusive prefix(lw)
    int packed = 0;
    #pragma unroll
    for (int q = 0; q < 4; ++q) {
        const int i = q * 128 + lane * 4;
        int4 dd = *(const int4*)(dbat + i);
        const int full = dd.x + dd.y + dd.z + dd.w;
        packed += full + (((i < lw) ? full : 0) << 16);
    }
    #pragma unroll
    for (int o = 16; o > 0; o >>= 1)
        packed += __shfl_xor_sync(0xffffffffu, packed, o);

    const int total = packed & 0xFFFF;
    const int prefw = packed >> 16;               // exclusive prefix at lw

    __syncthreads();                              // staging visible block-wide

    // ---- elected lane per warp issues bulk copies for its 4 phonemes
    if (lane == 0) {
        asm volatile("fence.proxy.async.shared::cta;" ::: "memory");

        const int4 dq = *(const int4*)(dbat + lw);
        const int dl[4] = { dq.x, dq.y, dq.z, dq.w };

        char* const obase = (char*)(out4 + (size_t)b * max_T * D4);
        int start = prefw;
        #pragma unroll
        for (int p = 0; p < 4; ++p) {
            const uint32_t src = smem_u32(&rows[(4 * w + p) * 2 * ROW_F4]);
            int rem = dl[p];
            int off = start;
            while (rem > 0) {
                const int  ch    = (rem >= 2) ? 2 : 1;
                const uint32_t bytes = (uint32_t)ch * FRAME_BYTES;
                char* gdst = obase + (size_t)off * FRAME_BYTES;
                asm volatile(
                    "cp.async.bulk.global.shared::cta.bulk_group [%0], [%1], %2;"
                    :: "l"(gdst), "r"(src), "r"(bytes) : "memory");
                rem -= ch;
                off += ch;
            }
            start += dl[p];
        }

        // ---- tail zeroing: strided share of [total, max_T), 1 frame per bulk
        const uint32_t zsrc = smem_u32(zrow);
        for (int f = total + blkLocal * 4 + w; f < max_T; f += 4 * BLOCKS_PER_BATCH) {
            char* gdst = obase + (size_t)f * FRAME_BYTES;
            asm volatile(
                "cp.async.bulk.global.shared::cta.bulk_group [%0], [%1], %2;"
                :: "l"(gdst), "r"(zsrc), "n"(FRAME_BYTES) : "memory");
        }

        asm volatile("cp.async.bulk.commit_group;" ::: "memory");
        asm volatile("cp.async.bulk.wait_group 0;" ::: "memory");
    }
}

extern "C" void kernel_launch(void* const* d_in, const int* in_sizes, int n_in,
                              void* d_out, int out_size) {
    const float* hidden    = (const float*)d_in[0];   // [B, L, D] fp32
    const int*   durations = (const int*)d_in[1];     // [B, L] int32
    float*       out       = (float*)d_out;

    const int max_T = out_size / (B_CONST * D_CONST);

    lr_fused<<<B_CONST * BLOCKS_PER_BATCH, THREADS>>>(
        (const float4*)hidden, durations, (float4*)out, max_T);
}

// round 11
// speedup vs baseline: 1.1078x; 1.1078x over previous
#include <cuda_runtime.h>
#include <cstdint>

// LengthRegulator: expand hidden_phonems [B,L,D] by durations [B,L] into
// out [B, max_T, D], zero-padded beyond totals[b].
//
// R11: ONE lean kernel. Block = 4 phonemes of one batch, 256 thr.
// Minimal front-end: warp-uniform int4 quad -> d + local offset; per-warp
// (total, prefix) via one packed accumulator + single REDUX.SUM
// (__reduce_add_sync) -- no smem, no barriers, low regs, high occupancy.
// Exact-trip warp-uniform STG.128 replication; strided tail zeroing.

#define B_CONST 32
#define L_CONST 512
#define D_CONST 256
#define D4 (D_CONST / 4)
#define P_PER_BLK 4
#define BLOCKS_PER_BATCH (L_CONST / P_PER_BLK)   // 128

__global__ void __launch_bounds__(256) lr_fused(
    const float4* __restrict__ hidden4,
    const int*    __restrict__ durations,
    float4*       __restrict__ out4,
    int max_T)
{
    const int t        = threadIdx.x;            // 0..255
    const int blk      = blockIdx.x;             // 0..4095
    const int b        = blk >> 7;               // batch
    const int blkLocal = blk & (BLOCKS_PER_BATCH - 1);
    const int l0       = blkLocal * P_PER_BLK;   // multiple of 4
    const int fgrp     = t >> 6;                 // phoneme lane-group [0,4)
    const int lane64   = t & 63;                 // float4 lane over D
    const int lane     = t & 31;

    const int* __restrict__ dbat = durations + b * L_CONST;

    // ---- row load issued first; latency hides under the reduction below
    const float4 v = hidden4[((size_t)b * L_CONST + l0 + fgrp) * D4 + lane64];

    // ---- my duration + offset within the block (one warp-uniform int4)
    const int4 q = *(const int4*)(dbat + l0);
    const int d     = (fgrp == 0) ? q.x : (fgrp == 1) ? q.y : (fgrp == 2) ? q.z : q.w;
    const int local = ((fgrp > 0) ? q.x : 0) + ((fgrp > 1) ? q.y : 0)
                    + ((fgrp > 2) ? q.z : 0);

    // ---- packed per-warp reduction over all 512 durations:
    //      low 16 bits = batch total, high 16 bits = exclusive prefix(l0).
    //      quad starts and l0 are multiples of 4 -> no straddle.
    unsigned packed = 0;
    #pragma unroll
    for (int p = 0; p < 4; ++p) {
        const int i = p * 128 + lane * 4;
        const int4 dd = *(const int4*)(dbat + i);
        const unsigned full = (unsigned)(dd.x + dd.y + dd.z + dd.w);
        packed += full + (((i < l0) ? full : 0u) << 16);
    }
    packed = __reduce_add_sync(0xffffffffu, packed);   // REDUX.SUM

    const int total = (int)(packed & 0xFFFFu);
    const int start = (int)(packed >> 16) + local;

    // ---- exact-trip replication: d warp-uniform coalesced STG.128
    float4* __restrict__ obase = out4 + (size_t)b * max_T * D4 + lane64;
    float4* dst = obase + (size_t)start * D4;
    for (int j = 0; j < d; ++j)
        dst[j * D4] = v;

    // ---- tail zeroing: this block's strided share of [total, max_T)
    const float4 zero = make_float4(0.f, 0.f, 0.f, 0.f);
    for (int f = total + blkLocal * 4 + fgrp; f < max_T; f += 4 * BLOCKS_PER_BATCH) {
        obase[(size_t)f * D4] = zero;
    }
}

extern "C" void kernel_launch(void* const* d_in, const int* in_sizes, int n_in,
                              void* d_out, int out_size) {
    const float* hidden    = (const float*)d_in[0];   // [B, L, D] fp32
    const int*   durations = (const int*)d_in[1];     // [B, L] int32
    float*       out       = (float*)d_out;

    const int max_T = out_size / (B_CONST * D_CONST);

    lr_fused<<<B_CONST * BLOCKS_PER_BATCH, 256>>>(
        (const float4*)hidden, durations, (float4*)out, max_T);
}

// round 12
// speedup vs baseline: 1.1102x; 1.0022x over previous
#include <cuda_runtime.h>
#include <cstdint>

// LengthRegulator: expand hidden_phonems [B,L,D] by durations [B,L] into
// out [B, max_T, D], zero-padded beyond totals[b].
//
// R12: R11 trimmed to the expand floor.
//  - reduction BEFORE the row load (int4 temps don't coexist with v -> fewer
//    regs, higher occupancy)
//  - switch(d) exact-unrolled store runs (no loop overhead, no dead predicated
//    issues)
//  - __stcs streaming stores (write-once output), __ldcs row loads (read-once)

#define B_CONST 32
#define L_CONST 512
#define D_CONST 256
#define D4 (D_CONST / 4)
#define P_PER_BLK 4
#define BLOCKS_PER_BATCH (L_CONST / P_PER_BLK)   // 128

__global__ void __launch_bounds__(256) lr_fused(
    const float4* __restrict__ hidden4,
    const int*    __restrict__ durations,
    float4*       __restrict__ out4,
    int max_T)
{
    const int t        = threadIdx.x;            // 0..255
    const int blk      = blockIdx.x;             // 0..4095
    const int b        = blk >> 7;               // batch
    const int blkLocal = blk & (BLOCKS_PER_BATCH - 1);
    const int l0       = blkLocal * P_PER_BLK;   // multiple of 4
    const int fgrp     = t >> 6;                 // phoneme lane-group [0,4)
    const int lane64   = t & 63;                 // float4 lane over D
    const int lane     = t & 31;

    const int* __restrict__ dbat = durations + b * L_CONST;

    // ---- packed per-warp reduction over all 512 durations:
    //      low 16 bits = batch total, high 16 bits = exclusive prefix(l0).
    unsigned packed = 0;
    #pragma unroll
    for (int p = 0; p < 4; ++p) {
        const int i = p * 128 + lane * 4;
        const int4 dd = *(const int4*)(dbat + i);
        const unsigned full = (unsigned)(dd.x + dd.y + dd.z + dd.w);
        packed += full + (((i < l0) ? full : 0u) << 16);
    }
    packed = __reduce_add_sync(0xffffffffu, packed);   // REDUX.SUM

    const int total = (int)(packed & 0xFFFFu);

    // ---- my duration + offset within the block (one warp-uniform int4)
    const int4 q = *(const int4*)(dbat + l0);
    const int d     = (fgrp == 0) ? q.x : (fgrp == 1) ? q.y : (fgrp == 2) ? q.z : q.w;
    const int local = ((fgrp > 0) ? q.x : 0) + ((fgrp > 1) ? q.y : 0)
                    + ((fgrp > 2) ? q.z : 0);
    const int start = (int)(packed >> 16) + local;

    // ---- row load (read-once: streaming)
    const float4 v = __ldcs(&hidden4[((size_t)b * L_CONST + l0 + fgrp) * D4 + lane64]);

    // ---- exact-unrolled replication runs (warp-uniform d, streaming stores)
    float4* __restrict__ obase = out4 + (size_t)b * max_T * D4 + lane64;
    float4* dst = obase + (size_t)start * D4;
    switch (d) {
        case 7: __stcs(dst + 6 * D4, v);  // fallthrough
        case 6: __stcs(dst + 5 * D4, v);
        case 5: __stcs(dst + 4 * D4, v);
        case 4: __stcs(dst + 3 * D4, v);
        case 3: __stcs(dst + 2 * D4, v);
        case 2: __stcs(dst + 1 * D4, v);
        case 1: __stcs(dst + 0 * D4, v);
        default: break;
    }

    // ---- tail zeroing: this block's strided share of [total, max_T)
    const float4 zero = make_float4(0.f, 0.f, 0.f, 0.f);
    for (int f = total + blkLocal * 4 + fgrp; f < max_T; f += 4 * BLOCKS_PER_BATCH) {
        __stcs(obase + (size_t)f * D4, zero);
    }
}

extern "C" void kernel_launch(void* const* d_in, const int* in_sizes, int n_in,
                              void* d_out, int out_size) {
    const float* hidden    = (const float*)d_in[0];   // [B, L, D] fp32
    const int*   durations = (const int*)d_in[1];     // [B, L] int32
    float*       out       = (float*)d_out;

    const int max_T = out_size / (B_CONST * D_CONST);

    lr_fused<<<B_CONST * BLOCKS_PER_BATCH, 256>>>(
        (const float4*)hidden, durations, (float4*)out, max_T);
}